// round 16
// baseline (speedup 1.0000x reference)
#include <cuda_runtime.h>

#define NMAX 100000
#define EMAX 1600000

typedef unsigned long long u64;

// ---------------- packed f32x2 helpers (Blackwell FFMA2) --------------------
__device__ __forceinline__ u64 ffma2(u64 a, u64 b, u64 c) {
    u64 d;
    asm("fma.rn.f32x2 %0, %1, %2, %3;" : "=l"(d) : "l"(a), "l"(b), "l"(c));
    return d;
}
__device__ __forceinline__ u64 bcast2(float a) {
    u64 r;
    asm("mov.b64 %0, {%1, %1};" : "=l"(r) : "f"(a));
    return r;
}
__device__ __forceinline__ u64 pack2f(float lo, float hi) {
    u64 r;
    asm("mov.b64 %0, {%1, %2};" : "=l"(r) : "f"(lo), "f"(hi));
    return r;
}
__device__ __forceinline__ float2 unpack2(u64 v) {
    float lo, hi;
    asm("mov.b64 {%0, %1}, %2;" : "=f"(lo), "=f"(hi) : "l"(v));
    return make_float2(lo, hi);
}

// ---------------- scratch (device globals; zero-initialized at load) --------
__device__ float g_y1[NMAX * 64];   // gather0 output: single active channel
__device__ float g_y2[NMAX * 64];
__device__ float g_y4[NMAX * 64];
__device__ float g_xl[NMAX * 64];
__device__ float g_xh[NMAX * 64];
__device__ float2 g_D1[NMAX];
__device__ float2 g_D2[NMAX];
__device__ int    g_cnt[NMAX];   // packed (deg<<16)|s; zeroed by scanC for next replay
__device__ int    g_deg[NMAX];
__device__ int    g_ptr[NMAX];
__device__ int    g_pos[NMAX];
__device__ int    g_adj[EMAX];
__device__ int    g_ecc[EMAX];   // (c<<1)|cc[c], or -1 for self-loops
__device__ int    g_bsum[128];

// ---------------- degree pass (packed atomic + edge-packed cc) --------------
__global__ void k_deg(const int* __restrict__ col, const int* __restrict__ row,
                      const int* __restrict__ cc, int E) {
    int e = blockIdx.x * blockDim.x + threadIdx.x;
    if (e >= E) return;
    int r = __ldg(row + e);
    int c = __ldg(col + e);
    if (r == c) { g_ecc[e] = -1; return; }
    int cv = __ldg(cc + c);
    g_ecc[e] = (c << 1) | cv;
    atomicAdd(&g_cnt[r], 0x10000 | cv);
}

// ---------------- scan kernel A: per-1024-chunk sums ------------------------
__global__ void k_scanA(int n) {
    __shared__ int sm[1024];
    int tid = threadIdx.x;
    int i = blockIdx.x * 1024 + tid;
    int v = (i < n) ? (g_cnt[i] >> 16) : 0;
    sm[tid] = v;
    __syncthreads();
    for (int off = 512; off; off >>= 1) {
        if (tid < off) sm[tid] += sm[tid + off];
        __syncthreads();
    }
    if (tid == 0) g_bsum[blockIdx.x] = sm[0];
}

// ---------------- scan kernel C: ptr/pos + coefficients + self-zeroing ------
__global__ void k_scanC(const int* __restrict__ cc, int n) {
    __shared__ int ws[32];
    __shared__ int s_boff;
    int tid = threadIdx.x;
    int lane = tid & 31, w = tid >> 5;

    if (w == 0) {
        int acc = 0;
        for (int j = lane; j < blockIdx.x; j += 32) acc += g_bsum[j];
#pragma unroll
        for (int o = 16; o; o >>= 1) acc += __shfl_xor_sync(0xffffffffu, acc, o);
        if (lane == 0) s_boff = acc;
    }

    int i = blockIdx.x * 1024 + tid;
    int packed = (i < n) ? g_cnt[i] : 0;
    int v = packed >> 16;
    int xv = v;
    const unsigned F = 0xffffffffu;
#pragma unroll
    for (int o = 1; o < 32; o <<= 1) {
        int y = __shfl_up_sync(F, xv, o);
        if (lane >= o) xv += y;
    }
    if (lane == 31) ws[w] = xv;
    __syncthreads();
    if (w == 0) {
        int t2 = ws[lane];
        int sv = t2;
#pragma unroll
        for (int o = 1; o < 32; o <<= 1) {
            int y = __shfl_up_sync(F, sv, o);
            if (lane >= o) sv += y;
        }
        ws[lane] = sv - t2;
    }
    __syncthreads();
    if (i < n) {
        int ptr = s_boff + ws[w] + xv - v;
        g_ptr[i] = ptr;
        g_pos[i] = ptr;
        g_deg[i] = v;
        g_cnt[i] = 0;                 // ready for next replay
        float cnt = (float)v;
        float sv2 = (float)(packed & 0xffff);
        int cci = __ldg(cc + i);
        float dl  = rsqrtf((cci ? cnt : 0.f) + 1.f);
        float dh  = rsqrtf((cci ? 0.f : cnt) + 1.f);
        float dll = rsqrtf(sv2 + 1.f);
        float dhh = rsqrtf(cnt - sv2 + 1.f);
        g_D1[i] = make_float2(dl, dh);
        g_D2[i] = make_float2(dll, dhh);
    }
}

// ---------------- scatter: build adjacency (sequential reads only) ----------
__global__ void k_scatter(const int* __restrict__ row, int E) {
    int e = blockIdx.x * blockDim.x + threadIdx.x;
    if (e >= E) return;
    int ec = g_ecc[e];
    if (ec < 0) return;
    int r = __ldg(row + e);
    int p = atomicAdd(&g_pos[r], 1);
    g_adj[p] = ec;
}

// ---------------- gather pass 0: quad scheme (4 neighbors / warp-iter) ------
__global__ void __launch_bounds__(256) k_gather0(const int* __restrict__ cc,
                                                 const float* __restrict__ x,
                                                 int n) {
    int tid = threadIdx.x;
    int warp = tid >> 5, l = tid & 31;
    int r = blockIdx.x * 8 + warp;
    if (r >= n) return;
    int quad = l >> 3, q = l & 7;   // 8 lanes per neighbor; lane covers 32B

    int ccr = __ldg(cc + r);
    float2 d1r = g_D1[r];
    float drv = ccr ? d1r.x : d1r.y;
    int start = g_ptr[r];
    int deg = g_deg[r];

    u64 acc0 = 0ull, acc1 = 0ull, acc2 = 0ull, acc3 = 0ull;
    const unsigned F = 0xffffffffu;
    for (int j0 = 0; j0 < deg; j0 += 32) {
        int myp = 0; float myw = 0.f;
        if (j0 + l < deg) {
            myp = __ldg(g_adj + start + j0 + l);
            float2 d1c = __ldg(&g_D1[myp >> 1]);
            myw = drv * (ccr ? d1c.x : d1c.y);
        }
        int kmax = deg - j0; if (kmax > 32) kmax = 32;
        int quads = (kmax + 3) >> 2;
#pragma unroll 4
        for (int k = 0; k < quads; k++) {
            int idx = 4 * k + quad;
            int c = __shfl_sync(F, myp, idx) >> 1;   // myw==0 for idx>=kmax lanes
            float w = __shfl_sync(F, myw, idx);
            u64 wp = bcast2(w);
            const ulonglong2* src = (const ulonglong2*)(x + c * 64);
            ulonglong2 v0 = __ldg(src + 2 * q);
            ulonglong2 v1 = __ldg(src + 2 * q + 1);
            acc0 = ffma2(wp, v0.x, acc0);
            acc1 = ffma2(wp, v0.y, acc1);
            acc2 = ffma2(wp, v1.x, acc2);
            acc3 = ffma2(wp, v1.y, acc3);
        }
    }
    float2 p0 = unpack2(acc0), p1 = unpack2(acc1);
    float2 p2 = unpack2(acc2), p3 = unpack2(acc3);
#pragma unroll
    for (int o = 8; o <= 16; o <<= 1) {
        p0.x += __shfl_xor_sync(F, p0.x, o);
        p0.y += __shfl_xor_sync(F, p0.y, o);
        p1.x += __shfl_xor_sync(F, p1.x, o);
        p1.y += __shfl_xor_sync(F, p1.y, o);
        p2.x += __shfl_xor_sync(F, p2.x, o);
        p2.y += __shfl_xor_sync(F, p2.y, o);
        p3.x += __shfl_xor_sync(F, p3.x, o);
        p3.y += __shfl_xor_sync(F, p3.y, o);
    }
    if (quad == 0) {
        float4* dst = (float4*)(g_y1 + r * 64);
        dst[2 * q]     = make_float4(p0.x, p0.y, p1.x, p1.y);
        dst[2 * q + 1] = make_float4(p2.x, p2.y, p3.x, p3.y);
    }
}

// ---------------- gather pass 1: quad scheme, per-quad channel branch -------
__global__ void __launch_bounds__(256) k_gather1(int n) {
    int tid = threadIdx.x;
    int warp = tid >> 5, l = tid & 31;
    int r = blockIdx.x * 8 + warp;
    if (r >= n) return;
    int quad = l >> 3, q = l & 7;

    float2 d2r = g_D2[r];
    float dllr = d2r.x, dhhr = d2r.y;
    int start = g_ptr[r];
    int deg = g_deg[r];

    u64 a2[4] = {0ull, 0ull, 0ull, 0ull};
    u64 a4[4] = {0ull, 0ull, 0ull, 0ull};
    const unsigned F = 0xffffffffu;
    for (int j0 = 0; j0 < deg; j0 += 32) {
        int myp = 0; float myw = 0.f;
        if (j0 + l < deg) {
            myp = __ldg(g_adj + start + j0 + l);
            float2 d2c = __ldg(&g_D2[myp >> 1]);
            myw = (myp & 1) ? dllr * d2c.x : dhhr * d2c.y;
        }
        int kmax = deg - j0; if (kmax > 32) kmax = 32;
        int quads = (kmax + 3) >> 2;
#pragma unroll 4
        for (int k = 0; k < quads; k++) {
            int idx = 4 * k + quad;
            int packed = __shfl_sync(F, myp, idx);
            float w = __shfl_sync(F, myw, idx);
            int c = packed >> 1;
            u64 wp = bcast2(w);
            if (packed & 1) {
                const ulonglong2* src = (const ulonglong2*)(g_xl + c * 64);
                ulonglong2 v0 = __ldg(src + 2 * q);
                ulonglong2 v1 = __ldg(src + 2 * q + 1);
                a2[0] = ffma2(wp, v0.x, a2[0]);
                a2[1] = ffma2(wp, v0.y, a2[1]);
                a2[2] = ffma2(wp, v1.x, a2[2]);
                a2[3] = ffma2(wp, v1.y, a2[3]);
            } else {
                const ulonglong2* src = (const ulonglong2*)(g_xh + c * 64);
                ulonglong2 v0 = __ldg(src + 2 * q);
                ulonglong2 v1 = __ldg(src + 2 * q + 1);
                a4[0] = ffma2(wp, v0.x, a4[0]);
                a4[1] = ffma2(wp, v0.y, a4[1]);
                a4[2] = ffma2(wp, v1.x, a4[2]);
                a4[3] = ffma2(wp, v1.y, a4[3]);
            }
        }
    }
    float2 s2[4], s4[4];
#pragma unroll
    for (int j = 0; j < 4; j++) { s2[j] = unpack2(a2[j]); s4[j] = unpack2(a4[j]); }
#pragma unroll
    for (int o = 8; o <= 16; o <<= 1) {
#pragma unroll
        for (int j = 0; j < 4; j++) {
            s2[j].x += __shfl_xor_sync(F, s2[j].x, o);
            s2[j].y += __shfl_xor_sync(F, s2[j].y, o);
            s4[j].x += __shfl_xor_sync(F, s4[j].x, o);
            s4[j].y += __shfl_xor_sync(F, s4[j].y, o);
        }
    }
    if (quad == 0) {
        float4* d2 = (float4*)(g_y2 + r * 64);
        float4* d4 = (float4*)(g_y4 + r * 64);
        d2[2 * q]     = make_float4(s2[0].x, s2[0].y, s2[1].x, s2[1].y);
        d2[2 * q + 1] = make_float4(s2[2].x, s2[2].y, s2[3].x, s2[3].y);
        d4[2 * q]     = make_float4(s4[0].x, s4[0].y, s4[1].x, s4[1].y);
        d4[2 * q + 1] = make_float4(s4[2].x, s4[2].y, s4[3].x, s4[3].y);
    }
}

// ---------------- dense layer 1: single-pass (x staged once) ----------------
#define D1_SMEM_FLOATS (4 * 4096 + 3 * 128 * 17)
__global__ void __launch_bounds__(256, 2) k_dense1(const float* __restrict__ x,
                                                   const int* __restrict__ cc,
                                                   const float* __restrict__ W1l,
                                                   const float* __restrict__ W1r,
                                                   const float* __restrict__ W3l,
                                                   const float* __restrict__ W3r,
                                                   int n) {
    extern __shared__ float s[];
    float* sw1l = s;
    float* sw1r = s + 4096;
    float* sw3l = s + 8192;
    float* sw3r = s + 12288;
    float* bufA = s + 16384;
    float* bufB = bufA + 128 * 17;
    float* bufC = bufB + 128 * 17;

    int tid = threadIdx.x;
    {
        float4* d4 = (float4*)s;
        for (int i = tid; i < 4096; i += 256) {
            const float* srcm = (i < 1024) ? W1l : (i < 2048) ? W1r : (i < 3072) ? W3l : W3r;
            d4[i] = ((const float4*)srcm)[i & 1023];
        }
    }

    int tn = tid & 7;
    int tm = tid >> 3;
    int nbase = blockIdx.x * 128;

    u64 accL[4][4], accH[4][4];
#pragma unroll
    for (int i = 0; i < 4; i++)
#pragma unroll
        for (int j = 0; j < 4; j++) { accL[i][j] = 0ull; accH[i][j] = 0ull; }

    for (int c = 0; c < 4; c++) {
        __syncthreads();
        for (int it = tid; it < 512; it += 256) {
            int nl = it >> 2, f4 = it & 3;
            int node = nbase + nl;
            int kg = c * 16 + f4 * 4;
            float4 xv = make_float4(0.f, 0.f, 0.f, 0.f), yv = xv;
            float dl2 = 0.f, dh2 = 0.f, m1 = 0.f;
            if (node < n) {
                xv = __ldg((const float4*)(x + node * 64 + kg));
                yv = *((const float4*)(g_y1 + node * 64 + kg));
                float2 d = g_D1[node];
                dl2 = d.x * d.x; dh2 = d.y * d.y;
                m1 = __ldg(cc + node) ? 1.f : 0.f;
            }
            float m3 = 1.f - m1;
            int sb = nl * 17 + f4 * 4;
            bufA[sb + 0] = m1 * yv.x + dl2 * xv.x;
            bufA[sb + 1] = m1 * yv.y + dl2 * xv.y;
            bufA[sb + 2] = m1 * yv.z + dl2 * xv.z;
            bufA[sb + 3] = m1 * yv.w + dl2 * xv.w;
            bufB[sb + 0] = m3 * yv.x + dh2 * xv.x;
            bufB[sb + 1] = m3 * yv.y + dh2 * xv.y;
            bufB[sb + 2] = m3 * yv.z + dh2 * xv.z;
            bufB[sb + 3] = m3 * yv.w + dh2 * xv.w;
            bufC[sb + 0] = xv.x; bufC[sb + 1] = xv.y;
            bufC[sb + 2] = xv.z; bufC[sb + 3] = xv.w;
        }
        __syncthreads();
        const float* wl  = sw1l + c * 16 * 64;
        const float* wr  = sw1r + c * 16 * 64;
        const float* whl = sw3l + c * 16 * 64;
        const float* whr = sw3r + c * 16 * 64;
#pragma unroll 8
        for (int k = 0; k < 16; k++) {
            u64 a1p[4], a3p[4], axp[4];
#pragma unroll
            for (int i = 0; i < 4; i++) {
                a1p[i] = bcast2(bufA[(tm * 4 + i) * 17 + k]);
                a3p[i] = bcast2(bufB[(tm * 4 + i) * 17 + k]);
                axp[i] = bcast2(bufC[(tm * 4 + i) * 17 + k]);
            }
            ulonglong2 l0 = *(const ulonglong2*)(wl + k * 64 + tn * 8);
            ulonglong2 l1 = *(const ulonglong2*)(wl + k * 64 + tn * 8 + 4);
            ulonglong2 r0 = *(const ulonglong2*)(wr + k * 64 + tn * 8);
            ulonglong2 r1 = *(const ulonglong2*)(wr + k * 64 + tn * 8 + 4);
            ulonglong2 h0 = *(const ulonglong2*)(whl + k * 64 + tn * 8);
            ulonglong2 h1 = *(const ulonglong2*)(whl + k * 64 + tn * 8 + 4);
            ulonglong2 g0 = *(const ulonglong2*)(whr + k * 64 + tn * 8);
            ulonglong2 g1 = *(const ulonglong2*)(whr + k * 64 + tn * 8 + 4);
#pragma unroll
            for (int i = 0; i < 4; i++) {
                accL[i][0] = ffma2(a1p[i], l0.x, accL[i][0]);
                accL[i][1] = ffma2(a1p[i], l0.y, accL[i][1]);
                accL[i][2] = ffma2(a1p[i], l1.x, accL[i][2]);
                accL[i][3] = ffma2(a1p[i], l1.y, accL[i][3]);
                accL[i][0] = ffma2(axp[i], r0.x, accL[i][0]);
                accL[i][1] = ffma2(axp[i], r0.y, accL[i][1]);
                accL[i][2] = ffma2(axp[i], r1.x, accL[i][2]);
                accL[i][3] = ffma2(axp[i], r1.y, accL[i][3]);
                accH[i][0] = ffma2(a3p[i], h0.x, accH[i][0]);
                accH[i][1] = ffma2(a3p[i], h0.y, accH[i][1]);
                accH[i][2] = ffma2(a3p[i], h1.x, accH[i][2]);
                accH[i][3] = ffma2(a3p[i], h1.y, accH[i][3]);
                accH[i][0] = ffma2(axp[i], g0.x, accH[i][0]);
                accH[i][1] = ffma2(axp[i], g0.y, accH[i][1]);
                accH[i][2] = ffma2(axp[i], g1.x, accH[i][2]);
                accH[i][3] = ffma2(axp[i], g1.y, accH[i][3]);
            }
        }
    }

#pragma unroll
    for (int i = 0; i < 4; i++) {
        int node = nbase + tm * 4 + i;
        if (node >= n) continue;
        float2 p0 = unpack2(accL[i][0]), p1 = unpack2(accL[i][1]);
        float2 p2 = unpack2(accL[i][2]), p3 = unpack2(accL[i][3]);
        float4 v0 = make_float4(fmaxf(p0.x, 0.f), fmaxf(p0.y, 0.f),
                                fmaxf(p1.x, 0.f), fmaxf(p1.y, 0.f));
        float4 v1 = make_float4(fmaxf(p2.x, 0.f), fmaxf(p2.y, 0.f),
                                fmaxf(p3.x, 0.f), fmaxf(p3.y, 0.f));
        *((float4*)(g_xl + node * 64 + tn * 8))     = v0;
        *((float4*)(g_xl + node * 64 + tn * 8 + 4)) = v1;
        p0 = unpack2(accH[i][0]); p1 = unpack2(accH[i][1]);
        p2 = unpack2(accH[i][2]); p3 = unpack2(accH[i][3]);
        v0 = make_float4(fmaxf(p0.x, 0.f), fmaxf(p0.y, 0.f),
                         fmaxf(p1.x, 0.f), fmaxf(p1.y, 0.f));
        v1 = make_float4(fmaxf(p2.x, 0.f), fmaxf(p2.y, 0.f),
                         fmaxf(p3.x, 0.f), fmaxf(p3.y, 0.f));
        *((float4*)(g_xh + node * 64 + tn * 8))     = v0;
        *((float4*)(g_xh + node * 64 + tn * 8 + 4)) = v1;
    }
}

// ---------------- dense layer 2: merged phases 1+2 (xl/xh staged once) ------
#define D2_SMEM_FLOATS (5 * 4096 + 4 * 64 * 17 + 2560 + 40)
__global__ void __launch_bounds__(256, 2) k_dense2(const float* __restrict__ x,
                                                   const int* __restrict__ cc,
                                                   const float* __restrict__ W2l,
                                                   const float* __restrict__ W2r,
                                                   const float* __restrict__ W4l,
                                                   const float* __restrict__ W4r,
                                                   const float* __restrict__ WX,
                                                   const float* __restrict__ lam1,
                                                   const float* __restrict__ lam2,
                                                   const float* __restrict__ linW,
                                                   const float* __restrict__ linB,
                                                   float* __restrict__ out, int n) {
    extern __shared__ float s[];
    float* sw2l = s;
    float* sw2r = s + 4096;
    float* sw4l = s + 8192;
    float* sw4r = s + 12288;
    float* swx  = s + 16384;
    float* bufA = s + 20480;
    float* bufB = bufA + 64 * 17;
    float* bufC = bufB + 64 * 17;
    float* bufD = bufC + 64 * 17;
    float* sxf  = bufA;
    float* slin  = s + 20480 + 4 * 64 * 17;
    float* slinb = slin + 2560;

    int tid = threadIdx.x;
    {
        float4* d4 = (float4*)s;
        for (int i = tid; i < 5120; i += 256) {
            const float* srcm = (i < 1024) ? W2l : (i < 2048) ? W2r :
                                (i < 3072) ? W4l : (i < 4096) ? W4r : WX;
            d4[i] = ((const float4*)srcm)[i & 1023];
        }
        float4* l4 = (float4*)slin;
        for (int i = tid; i < 640; i += 256) l4[i] = ((const float4*)linW)[i];
        if (tid < 40) slinb[tid] = linB[tid];
    }

    int tn = tid & 15;
    int tm = tid >> 4;
    int nbase = blockIdx.x * 64;

    u64 accZ2[4][2], accZ4[4][2], accM[4][2];
#pragma unroll
    for (int i = 0; i < 4; i++)
#pragma unroll
        for (int j = 0; j < 2; j++) { accZ2[i][j] = 0ull; accZ4[i][j] = 0ull; accM[i][j] = 0ull; }

    for (int c = 0; c < 4; c++) {
        __syncthreads();
        {
            int it = tid;
            int nl = it >> 2, f4 = it & 3;
            int node = nbase + nl;
            int kg = c * 16 + f4 * 4;
            float4 xlv = make_float4(0.f, 0.f, 0.f, 0.f), xhv = xlv, y2v = xlv, y4v = xlv;
            float dll2 = 0.f, dhh2 = 0.f;
            if (node < n) {
                xlv = *((const float4*)(g_xl + node * 64 + kg));
                xhv = *((const float4*)(g_xh + node * 64 + kg));
                y2v = *((const float4*)(g_y2 + node * 64 + kg));
                y4v = *((const float4*)(g_y4 + node * 64 + kg));
                float2 d = g_D2[node];
                dll2 = d.x * d.x; dhh2 = d.y * d.y;
            }
            int sb = nl * 17 + f4 * 4;
            bufA[sb + 0] = y2v.x + dll2 * xlv.x;
            bufA[sb + 1] = y2v.y + dll2 * xlv.y;
            bufA[sb + 2] = y2v.z + dll2 * xlv.z;
            bufA[sb + 3] = y2v.w + dll2 * xlv.w;
            bufB[sb + 0] = y4v.x + dhh2 * xhv.x;
            bufB[sb + 1] = y4v.y + dhh2 * xhv.y;
            bufB[sb + 2] = y4v.z + dhh2 * xhv.z;
            bufB[sb + 3] = y4v.w + dhh2 * xhv.w;
            bufC[sb + 0] = xlv.x; bufC[sb + 1] = xlv.y;
            bufC[sb + 2] = xlv.z; bufC[sb + 3] = xlv.w;
            bufD[sb + 0] = xhv.x; bufD[sb + 1] = xhv.y;
            bufD[sb + 2] = xhv.z; bufD[sb + 3] = xhv.w;
        }
        __syncthreads();
        const float* w2l = sw2l + c * 16 * 64;
        const float* w2r = sw2r + c * 16 * 64;
        const float* w4l = sw4l + c * 16 * 64;
        const float* w4r = sw4r + c * 16 * 64;
#pragma unroll 8
        for (int k = 0; k < 16; k++) {
            u64 a2p[4], a4p[4], xlp[4], xhp[4];
#pragma unroll
            for (int i = 0; i < 4; i++) {
                a2p[i] = bcast2(bufA[(tm * 4 + i) * 17 + k]);
                a4p[i] = bcast2(bufB[(tm * 4 + i) * 17 + k]);
                xlp[i] = bcast2(bufC[(tm * 4 + i) * 17 + k]);
                xhp[i] = bcast2(bufD[(tm * 4 + i) * 17 + k]);
            }
            ulonglong2 wz2l = *(const ulonglong2*)(w2l + k * 64 + tn * 4);
            ulonglong2 wz2r = *(const ulonglong2*)(w2r + k * 64 + tn * 4);
            ulonglong2 wz4l = *(const ulonglong2*)(w4l + k * 64 + tn * 4);
            ulonglong2 wz4r = *(const ulonglong2*)(w4r + k * 64 + tn * 4);
#pragma unroll
            for (int i = 0; i < 4; i++) {
                accZ2[i][0] = ffma2(a2p[i], wz2l.x, accZ2[i][0]);
                accZ2[i][1] = ffma2(a2p[i], wz2l.y, accZ2[i][1]);
                accZ2[i][0] = ffma2(xlp[i], wz2r.x, accZ2[i][0]);
                accZ2[i][1] = ffma2(xlp[i], wz2r.y, accZ2[i][1]);
                accZ4[i][0] = ffma2(a4p[i], wz4l.x, accZ4[i][0]);
                accZ4[i][1] = ffma2(a4p[i], wz4l.y, accZ4[i][1]);
                accZ4[i][0] = ffma2(xhp[i], wz4r.x, accZ4[i][0]);
                accZ4[i][1] = ffma2(xhp[i], wz4r.y, accZ4[i][1]);
            }
        }
    }

    for (int c = 0; c < 4; c++) {
        __syncthreads();
        {
            int it = tid;
            int nl = it >> 2, f4 = it & 3;
            int node = nbase + nl;
            int kg = c * 16 + f4 * 4;
            float4 xv = make_float4(0.f, 0.f, 0.f, 0.f);
            if (node < n) xv = __ldg((const float4*)(x + node * 64 + kg));
            int sb = nl * 17 + f4 * 4;
            bufA[sb + 0] = xv.x; bufA[sb + 1] = xv.y;
            bufA[sb + 2] = xv.z; bufA[sb + 3] = xv.w;
        }
        __syncthreads();
        const float* wm = swx + c * 16 * 64;
#pragma unroll 8
        for (int k = 0; k < 16; k++) {
            u64 ap[4];
#pragma unroll
            for (int i = 0; i < 4; i++) ap[i] = bcast2(bufA[(tm * 4 + i) * 17 + k]);
            ulonglong2 wv = *(const ulonglong2*)(wm + k * 64 + tn * 4);
#pragma unroll
            for (int i = 0; i < 4; i++) {
                accM[i][0] = ffma2(ap[i], wv.x, accM[i][0]);
                accM[i][1] = ffma2(ap[i], wv.y, accM[i][1]);
            }
        }
    }

    float e0 = __expf(__ldg(lam1)), e1 = __expf(__ldg(lam1 + 1));
    float lamxl = e0 / (e0 + e1), laml = e1 / (e0 + e1);
    float f0 = __expf(__ldg(lam2)), f1 = __expf(__ldg(lam2 + 1));
    float lamxh = f0 / (f0 + f1), lamh = f1 / (f0 + f1);

    __syncthreads();
#pragma unroll
    for (int i = 0; i < 4; i++) {
        int node = nbase + tm * 4 + i;
        float lamx = (node < n && __ldg(cc + node)) ? lamxl : lamxh;
        float* st = sxf + (tm * 4 + i) * 65 + tn * 4;
#pragma unroll
        for (int j = 0; j < 2; j++) {
            float2 m = unpack2(accM[i][j]);
            float2 z2 = unpack2(accZ2[i][j]);
            float2 z4 = unpack2(accZ4[i][j]);
            st[2 * j + 0] = fmaxf(lamx * m.x + laml * z2.x + lamh * z4.x, 0.f);
            st[2 * j + 1] = fmaxf(lamx * m.y + laml * z2.y + lamh * z4.y, 0.f);
        }
    }
    __syncthreads();

    int nl2 = tid >> 2;
    int og  = (tid & 3) * 10;
    int node = nbase + nl2;
    if (node < n) {
        u64 accv[5];
#pragma unroll
        for (int j = 0; j < 5; j++) accv[j] = pack2f(slinb[og + 2 * j], slinb[og + 2 * j + 1]);
        const float* xr = sxf + nl2 * 65;
#pragma unroll 8
        for (int k = 0; k < 64; k++) {
            u64 bp = bcast2(xr[k]);
            const u64* wr = (const u64*)(slin + k * 40 + og);
#pragma unroll
            for (int j = 0; j < 5; j++) accv[j] = ffma2(bp, wr[j], accv[j]);
        }
#pragma unroll
        for (int j = 0; j < 5; j++) {
            float2 p = unpack2(accv[j]);
            out[node * 40 + og + 2 * j]     = p.x;
            out[node * 40 + og + 2 * j + 1] = p.y;
        }
    }
}

// ---------------- host launcher --------------------------------------------
extern "C" void kernel_launch(void* const* d_in, const int* in_sizes, int n_in,
                              void* d_out, int out_size) {
    const float* x    = (const float*)d_in[0];
    const int*   ei   = (const int*)d_in[1];
    const int*   cc   = (const int*)d_in[2];
    const float* W1l  = (const float*)d_in[3];
    const float* W1r  = (const float*)d_in[4];
    const float* W2l  = (const float*)d_in[5];
    const float* W2r  = (const float*)d_in[6];
    const float* W3l  = (const float*)d_in[7];
    const float* W3r  = (const float*)d_in[8];
    const float* W4l  = (const float*)d_in[9];
    const float* W4r  = (const float*)d_in[10];
    const float* WX   = (const float*)d_in[11];
    const float* lam1 = (const float*)d_in[12];
    const float* lam2 = (const float*)d_in[13];
    const float* linW = (const float*)d_in[14];
    const float* linB = (const float*)d_in[15];
    float* out = (float*)d_out;

    int n = in_sizes[0] / 64;
    int E = in_sizes[1] / 2;
    const int* col = ei;
    const int* row = ei + E;
    int nblk = (n + 1023) / 1024;

    cudaFuncSetAttribute(k_dense1, cudaFuncAttributeMaxDynamicSharedMemorySize,
                         D1_SMEM_FLOATS * 4);
    cudaFuncSetAttribute(k_dense2, cudaFuncAttributeMaxDynamicSharedMemorySize,
                         D2_SMEM_FLOATS * 4);

    k_deg<<<(E + 255) / 256, 256>>>(col, row, cc, E);
    k_scanA<<<nblk, 1024>>>(n);
    k_scanC<<<nblk, 1024>>>(cc, n);
    k_scatter<<<(E + 255) / 256, 256>>>(row, E);
    k_gather0<<<(n + 7) / 8, 256>>>(cc, x, n);
    k_dense1<<<(n + 127) / 128, 256, D1_SMEM_FLOATS * 4>>>(x, cc, W1l, W1r, W3l, W3r, n);
    k_gather1<<<(n + 7) / 8, 256>>>(n);
    k_dense2<<<(n + 63) / 64, 256, D2_SMEM_FLOATS * 4>>>(x, cc, W2l, W2r, W4l, W4r,
                                                         WX, lam1, lam2, linW, linB,
                                                         out, n);
}

// round 17
// speedup vs baseline: 1.0636x; 1.0636x over previous
#include <cuda_runtime.h>

#define NMAX 100000
#define EMAX 1600000

typedef unsigned long long u64;

// ---------------- packed f32x2 helpers (Blackwell FFMA2) --------------------
__device__ __forceinline__ u64 ffma2(u64 a, u64 b, u64 c) {
    u64 d;
    asm("fma.rn.f32x2 %0, %1, %2, %3;" : "=l"(d) : "l"(a), "l"(b), "l"(c));
    return d;
}
__device__ __forceinline__ u64 bcast2(float a) {
    u64 r;
    asm("mov.b64 %0, {%1, %1};" : "=l"(r) : "f"(a));
    return r;
}
__device__ __forceinline__ u64 pack2f(float lo, float hi) {
    u64 r;
    asm("mov.b64 %0, {%1, %2};" : "=l"(r) : "f"(lo), "f"(hi));
    return r;
}
__device__ __forceinline__ float2 unpack2(u64 v) {
    float lo, hi;
    asm("mov.b64 {%0, %1}, %2;" : "=f"(lo), "=f"(hi) : "l"(v));
    return make_float2(lo, hi);
}

// ---------------- scratch (device globals; zero-initialized at load) --------
__device__ float g_y1[NMAX * 64];   // gather0 output: single active channel
__device__ float g_y2[NMAX * 64];
__device__ float g_y4[NMAX * 64];
__device__ float g_xl[NMAX * 64];
__device__ float g_xh[NMAX * 64];
__device__ float2 g_D1[NMAX];
__device__ float2 g_D2[NMAX];
__device__ int    g_cnt[NMAX];   // packed (deg<<16)|s; zeroed by scanC for next replay
__device__ int    g_deg[NMAX];
__device__ int    g_sv[NMAX];    // per-row channel split point (count of cc=1 nbrs)
__device__ int    g_ptr[NMAX];
__device__ int    g_pos[NMAX];   // front counter (cc=1 edges)
__device__ int    g_pos2[NMAX];  // back counter (cc=0 edges)
__device__ int    g_adj[EMAX];   // plain neighbor index, channel-segregated per row
__device__ int    g_ecc[EMAX];   // (c<<1)|cc[c], or -1 for self-loops
__device__ int    g_bsum[128];

// ---------------- degree pass (packed atomic + edge-packed cc) --------------
__global__ void k_deg(const int* __restrict__ col, const int* __restrict__ row,
                      const int* __restrict__ cc, int E) {
    int e = blockIdx.x * blockDim.x + threadIdx.x;
    if (e >= E) return;
    int r = __ldg(row + e);
    int c = __ldg(col + e);
    if (r == c) { g_ecc[e] = -1; return; }
    int cv = __ldg(cc + c);
    g_ecc[e] = (c << 1) | cv;
    atomicAdd(&g_cnt[r], 0x10000 | cv);
}

// ---------------- scan kernel A: per-1024-chunk sums ------------------------
__global__ void k_scanA(int n) {
    __shared__ int sm[1024];
    int tid = threadIdx.x;
    int i = blockIdx.x * 1024 + tid;
    int v = (i < n) ? (g_cnt[i] >> 16) : 0;
    sm[tid] = v;
    __syncthreads();
    for (int off = 512; off; off >>= 1) {
        if (tid < off) sm[tid] += sm[tid + off];
        __syncthreads();
    }
    if (tid == 0) g_bsum[blockIdx.x] = sm[0];
}

// ---------------- scan kernel C: ptr/pos/pos2 + coefficients + self-zeroing -
__global__ void k_scanC(const int* __restrict__ cc, int n) {
    __shared__ int ws[32];
    __shared__ int s_boff;
    int tid = threadIdx.x;
    int lane = tid & 31, w = tid >> 5;

    if (w == 0) {
        int acc = 0;
        for (int j = lane; j < blockIdx.x; j += 32) acc += g_bsum[j];
#pragma unroll
        for (int o = 16; o; o >>= 1) acc += __shfl_xor_sync(0xffffffffu, acc, o);
        if (lane == 0) s_boff = acc;
    }

    int i = blockIdx.x * 1024 + tid;
    int packed = (i < n) ? g_cnt[i] : 0;
    int v = packed >> 16;
    int xv = v;
    const unsigned F = 0xffffffffu;
#pragma unroll
    for (int o = 1; o < 32; o <<= 1) {
        int y = __shfl_up_sync(F, xv, o);
        if (lane >= o) xv += y;
    }
    if (lane == 31) ws[w] = xv;
    __syncthreads();
    if (w == 0) {
        int t2 = ws[lane];
        int sv = t2;
#pragma unroll
        for (int o = 1; o < 32; o <<= 1) {
            int y = __shfl_up_sync(F, sv, o);
            if (lane >= o) sv += y;
        }
        ws[lane] = sv - t2;
    }
    __syncthreads();
    if (i < n) {
        int ptr = s_boff + ws[w] + xv - v;
        int sv2i = packed & 0xffff;
        g_ptr[i] = ptr;
        g_pos[i] = ptr;          // front: cc=1 edges
        g_pos2[i] = ptr + v;     // back:  cc=0 edges
        g_deg[i] = v;
        g_sv[i] = sv2i;
        g_cnt[i] = 0;            // ready for next replay
        float cnt = (float)v;
        float sv2 = (float)sv2i;
        int cci = __ldg(cc + i);
        float dl  = rsqrtf((cci ? cnt : 0.f) + 1.f);
        float dh  = rsqrtf((cci ? 0.f : cnt) + 1.f);
        float dll = rsqrtf(sv2 + 1.f);
        float dhh = rsqrtf(cnt - sv2 + 1.f);
        g_D1[i] = make_float2(dl, dh);
        g_D2[i] = make_float2(dll, dhh);
    }
}

// ---------------- scatter: channel-segregated adjacency ----------------------
__global__ void k_scatter(const int* __restrict__ row, int E) {
    int e = blockIdx.x * blockDim.x + threadIdx.x;
    if (e >= E) return;
    int ec = g_ecc[e];
    if (ec < 0) return;
    int r = __ldg(row + e);
    int p;
    if (ec & 1) p = atomicAdd(&g_pos[r], 1);
    else        p = atomicAdd(&g_pos2[r], -1) - 1;
    g_adj[p] = ec >> 1;
}

// ---------------- gather pass 0: single-channel output (order-insensitive) --
__global__ void __launch_bounds__(256) k_gather0(const int* __restrict__ cc,
                                                 const float* __restrict__ x,
                                                 int n) {
    int tid = threadIdx.x;
    int warp = tid >> 5, l = tid & 31;
    int r = blockIdx.x * 8 + warp;
    if (r >= n) return;
    int half = l >> 4, q = l & 15;

    int ccr = __ldg(cc + r);
    float2 d1r = g_D1[r];
    float drv = ccr ? d1r.x : d1r.y;
    int start = g_ptr[r];
    int deg = g_deg[r];

    u64 acc0 = 0ull, acc1 = 0ull;
    const unsigned F = 0xffffffffu;
    for (int j0 = 0; j0 < deg; j0 += 32) {
        int myc = 0; float myw = 0.f;
        if (j0 + l < deg) {
            myc = __ldg(g_adj + start + j0 + l);
            float2 d1c = __ldg(&g_D1[myc]);
            myw = drv * (ccr ? d1c.x : d1c.y);
        }
        int kmax = deg - j0; if (kmax > 32) kmax = 32;
        int pairs = (kmax + 1) >> 1;
#pragma unroll 4
        for (int k = 0; k < pairs; k++) {
            int idx = 2 * k + half;
            int c = __shfl_sync(F, myc, idx);
            float w = __shfl_sync(F, myw, idx);   // 0 for tail lanes
            u64 wp = bcast2(w);
            ulonglong2 v = __ldg((const ulonglong2*)(x + c * 64) + q);
            acc0 = ffma2(wp, v.x, acc0);
            acc1 = ffma2(wp, v.y, acc1);
        }
    }
    float2 p0 = unpack2(acc0), p1 = unpack2(acc1);
    p0.x += __shfl_xor_sync(F, p0.x, 16);
    p0.y += __shfl_xor_sync(F, p0.y, 16);
    p1.x += __shfl_xor_sync(F, p1.x, 16);
    p1.y += __shfl_xor_sync(F, p1.y, 16);
    if (half == 0)
        *((float4*)(g_y1 + r * 64) + q) = make_float4(p0.x, p0.y, p1.x, p1.y);
}

// ---------------- gather pass 1: two uniform loops (no channel branch) ------
__global__ void __launch_bounds__(256) k_gather1(int n) {
    int tid = threadIdx.x;
    int warp = tid >> 5, l = tid & 31;
    int r = blockIdx.x * 8 + warp;
    if (r >= n) return;
    int half = l >> 4, q = l & 15;

    float2 d2r = g_D2[r];
    float dllr = d2r.x, dhhr = d2r.y;
    int start = g_ptr[r];
    int sv = g_sv[r];
    int deg = g_deg[r];

    const unsigned F = 0xffffffffu;

    // segment 1: cc=1 neighbors [0, sv) -> g_xl, weight dllr * d2c.x
    u64 a20 = 0ull, a21 = 0ull;
    for (int j0 = 0; j0 < sv; j0 += 32) {
        int myc = 0; float myw = 0.f;
        if (j0 + l < sv) {
            myc = __ldg(g_adj + start + j0 + l);
            myw = dllr * __ldg(&g_D2[myc]).x;
        }
        int kmax = sv - j0; if (kmax > 32) kmax = 32;
        int pairs = (kmax + 1) >> 1;
#pragma unroll 4
        for (int k = 0; k < pairs; k++) {
            int idx = 2 * k + half;
            int c = __shfl_sync(F, myc, idx);
            float w = __shfl_sync(F, myw, idx);
            u64 wp = bcast2(w);
            ulonglong2 v = __ldg((const ulonglong2*)(g_xl + c * 64) + q);
            a20 = ffma2(wp, v.x, a20);
            a21 = ffma2(wp, v.y, a21);
        }
    }

    // segment 2: cc=0 neighbors [sv, deg) -> g_xh, weight dhhr * d2c.y
    u64 a40 = 0ull, a41 = 0ull;
    for (int j0 = sv; j0 < deg; j0 += 32) {
        int myc = 0; float myw = 0.f;
        if (j0 + l < deg) {
            myc = __ldg(g_adj + start + j0 + l);
            myw = dhhr * __ldg(&g_D2[myc]).y;
        }
        int kmax = deg - j0; if (kmax > 32) kmax = 32;
        int pairs = (kmax + 1) >> 1;
#pragma unroll 4
        for (int k = 0; k < pairs; k++) {
            int idx = 2 * k + half;
            int c = __shfl_sync(F, myc, idx);
            float w = __shfl_sync(F, myw, idx);
            u64 wp = bcast2(w);
            ulonglong2 v = __ldg((const ulonglong2*)(g_xh + c * 64) + q);
            a40 = ffma2(wp, v.x, a40);
            a41 = ffma2(wp, v.y, a41);
        }
    }

    float2 q20 = unpack2(a20), q21 = unpack2(a21);
    float2 q40 = unpack2(a40), q41 = unpack2(a41);
    q20.x += __shfl_xor_sync(F, q20.x, 16);
    q20.y += __shfl_xor_sync(F, q20.y, 16);
    q21.x += __shfl_xor_sync(F, q21.x, 16);
    q21.y += __shfl_xor_sync(F, q21.y, 16);
    q40.x += __shfl_xor_sync(F, q40.x, 16);
    q40.y += __shfl_xor_sync(F, q40.y, 16);
    q41.x += __shfl_xor_sync(F, q41.x, 16);
    q41.y += __shfl_xor_sync(F, q41.y, 16);
    if (half == 0) {
        *((float4*)(g_y2 + r * 64) + q) = make_float4(q20.x, q20.y, q21.x, q21.y);
        *((float4*)(g_y4 + r * 64) + q) = make_float4(q40.x, q40.y, q41.x, q41.y);
    }
}

// ---------------- dense layer 1: single-pass (x staged once) ----------------
#define D1_SMEM_FLOATS (4 * 4096 + 3 * 128 * 17)
__global__ void __launch_bounds__(256, 2) k_dense1(const float* __restrict__ x,
                                                   const int* __restrict__ cc,
                                                   const float* __restrict__ W1l,
                                                   const float* __restrict__ W1r,
                                                   const float* __restrict__ W3l,
                                                   const float* __restrict__ W3r,
                                                   int n) {
    extern __shared__ float s[];
    float* sw1l = s;
    float* sw1r = s + 4096;
    float* sw3l = s + 8192;
    float* sw3r = s + 12288;
    float* bufA = s + 16384;
    float* bufB = bufA + 128 * 17;
    float* bufC = bufB + 128 * 17;

    int tid = threadIdx.x;
    {
        float4* d4 = (float4*)s;
        for (int i = tid; i < 4096; i += 256) {
            const float* srcm = (i < 1024) ? W1l : (i < 2048) ? W1r : (i < 3072) ? W3l : W3r;
            d4[i] = ((const float4*)srcm)[i & 1023];
        }
    }

    int tn = tid & 7;
    int tm = tid >> 3;
    int nbase = blockIdx.x * 128;

    u64 accL[4][4], accH[4][4];
#pragma unroll
    for (int i = 0; i < 4; i++)
#pragma unroll
        for (int j = 0; j < 4; j++) { accL[i][j] = 0ull; accH[i][j] = 0ull; }

    for (int c = 0; c < 4; c++) {
        __syncthreads();
        for (int it = tid; it < 512; it += 256) {
            int nl = it >> 2, f4 = it & 3;
            int node = nbase + nl;
            int kg = c * 16 + f4 * 4;
            float4 xv = make_float4(0.f, 0.f, 0.f, 0.f), yv = xv;
            float dl2 = 0.f, dh2 = 0.f, m1 = 0.f;
            if (node < n) {
                xv = __ldg((const float4*)(x + node * 64 + kg));
                yv = *((const float4*)(g_y1 + node * 64 + kg));
                float2 d = g_D1[node];
                dl2 = d.x * d.x; dh2 = d.y * d.y;
                m1 = __ldg(cc + node) ? 1.f : 0.f;
            }
            float m3 = 1.f - m1;
            int sb = nl * 17 + f4 * 4;
            bufA[sb + 0] = m1 * yv.x + dl2 * xv.x;
            bufA[sb + 1] = m1 * yv.y + dl2 * xv.y;
            bufA[sb + 2] = m1 * yv.z + dl2 * xv.z;
            bufA[sb + 3] = m1 * yv.w + dl2 * xv.w;
            bufB[sb + 0] = m3 * yv.x + dh2 * xv.x;
            bufB[sb + 1] = m3 * yv.y + dh2 * xv.y;
            bufB[sb + 2] = m3 * yv.z + dh2 * xv.z;
            bufB[sb + 3] = m3 * yv.w + dh2 * xv.w;
            bufC[sb + 0] = xv.x; bufC[sb + 1] = xv.y;
            bufC[sb + 2] = xv.z; bufC[sb + 3] = xv.w;
        }
        __syncthreads();
        const float* wl  = sw1l + c * 16 * 64;
        const float* wr  = sw1r + c * 16 * 64;
        const float* whl = sw3l + c * 16 * 64;
        const float* whr = sw3r + c * 16 * 64;
#pragma unroll 8
        for (int k = 0; k < 16; k++) {
            u64 a1p[4], a3p[4], axp[4];
#pragma unroll
            for (int i = 0; i < 4; i++) {
                a1p[i] = bcast2(bufA[(tm * 4 + i) * 17 + k]);
                a3p[i] = bcast2(bufB[(tm * 4 + i) * 17 + k]);
                axp[i] = bcast2(bufC[(tm * 4 + i) * 17 + k]);
            }
            ulonglong2 l0 = *(const ulonglong2*)(wl + k * 64 + tn * 8);
            ulonglong2 l1 = *(const ulonglong2*)(wl + k * 64 + tn * 8 + 4);
            ulonglong2 r0 = *(const ulonglong2*)(wr + k * 64 + tn * 8);
            ulonglong2 r1 = *(const ulonglong2*)(wr + k * 64 + tn * 8 + 4);
            ulonglong2 h0 = *(const ulonglong2*)(whl + k * 64 + tn * 8);
            ulonglong2 h1 = *(const ulonglong2*)(whl + k * 64 + tn * 8 + 4);
            ulonglong2 g0 = *(const ulonglong2*)(whr + k * 64 + tn * 8);
            ulonglong2 g1 = *(const ulonglong2*)(whr + k * 64 + tn * 8 + 4);
#pragma unroll
            for (int i = 0; i < 4; i++) {
                accL[i][0] = ffma2(a1p[i], l0.x, accL[i][0]);
                accL[i][1] = ffma2(a1p[i], l0.y, accL[i][1]);
                accL[i][2] = ffma2(a1p[i], l1.x, accL[i][2]);
                accL[i][3] = ffma2(a1p[i], l1.y, accL[i][3]);
                accL[i][0] = ffma2(axp[i], r0.x, accL[i][0]);
                accL[i][1] = ffma2(axp[i], r0.y, accL[i][1]);
                accL[i][2] = ffma2(axp[i], r1.x, accL[i][2]);
                accL[i][3] = ffma2(axp[i], r1.y, accL[i][3]);
                accH[i][0] = ffma2(a3p[i], h0.x, accH[i][0]);
                accH[i][1] = ffma2(a3p[i], h0.y, accH[i][1]);
                accH[i][2] = ffma2(a3p[i], h1.x, accH[i][2]);
                accH[i][3] = ffma2(a3p[i], h1.y, accH[i][3]);
                accH[i][0] = ffma2(axp[i], g0.x, accH[i][0]);
                accH[i][1] = ffma2(axp[i], g0.y, accH[i][1]);
                accH[i][2] = ffma2(axp[i], g1.x, accH[i][2]);
                accH[i][3] = ffma2(axp[i], g1.y, accH[i][3]);
            }
        }
    }

#pragma unroll
    for (int i = 0; i < 4; i++) {
        int node = nbase + tm * 4 + i;
        if (node >= n) continue;
        float2 p0 = unpack2(accL[i][0]), p1 = unpack2(accL[i][1]);
        float2 p2 = unpack2(accL[i][2]), p3 = unpack2(accL[i][3]);
        float4 v0 = make_float4(fmaxf(p0.x, 0.f), fmaxf(p0.y, 0.f),
                                fmaxf(p1.x, 0.f), fmaxf(p1.y, 0.f));
        float4 v1 = make_float4(fmaxf(p2.x, 0.f), fmaxf(p2.y, 0.f),
                                fmaxf(p3.x, 0.f), fmaxf(p3.y, 0.f));
        *((float4*)(g_xl + node * 64 + tn * 8))     = v0;
        *((float4*)(g_xl + node * 64 + tn * 8 + 4)) = v1;
        p0 = unpack2(accH[i][0]); p1 = unpack2(accH[i][1]);
        p2 = unpack2(accH[i][2]); p3 = unpack2(accH[i][3]);
        v0 = make_float4(fmaxf(p0.x, 0.f), fmaxf(p0.y, 0.f),
                         fmaxf(p1.x, 0.f), fmaxf(p1.y, 0.f));
        v1 = make_float4(fmaxf(p2.x, 0.f), fmaxf(p2.y, 0.f),
                         fmaxf(p3.x, 0.f), fmaxf(p3.y, 0.f));
        *((float4*)(g_xh + node * 64 + tn * 8))     = v0;
        *((float4*)(g_xh + node * 64 + tn * 8 + 4)) = v1;
    }
}

// ---------------- dense layer 2: merged phases 1+2 (xl/xh staged once) ------
#define D2_SMEM_FLOATS (5 * 4096 + 4 * 64 * 17 + 2560 + 40)
__global__ void __launch_bounds__(256, 2) k_dense2(const float* __restrict__ x,
                                                   const int* __restrict__ cc,
                                                   const float* __restrict__ W2l,
                                                   const float* __restrict__ W2r,
                                                   const float* __restrict__ W4l,
                                                   const float* __restrict__ W4r,
                                                   const float* __restrict__ WX,
                                                   const float* __restrict__ lam1,
                                                   const float* __restrict__ lam2,
                                                   const float* __restrict__ linW,
                                                   const float* __restrict__ linB,
                                                   float* __restrict__ out, int n) {
    extern __shared__ float s[];
    float* sw2l = s;
    float* sw2r = s + 4096;
    float* sw4l = s + 8192;
    float* sw4r = s + 12288;
    float* swx  = s + 16384;
    float* bufA = s + 20480;
    float* bufB = bufA + 64 * 17;
    float* bufC = bufB + 64 * 17;
    float* bufD = bufC + 64 * 17;
    float* sxf  = bufA;
    float* slin  = s + 20480 + 4 * 64 * 17;
    float* slinb = slin + 2560;

    int tid = threadIdx.x;
    {
        float4* d4 = (float4*)s;
        for (int i = tid; i < 5120; i += 256) {
            const float* srcm = (i < 1024) ? W2l : (i < 2048) ? W2r :
                                (i < 3072) ? W4l : (i < 4096) ? W4r : WX;
            d4[i] = ((const float4*)srcm)[i & 1023];
        }
        float4* l4 = (float4*)slin;
        for (int i = tid; i < 640; i += 256) l4[i] = ((const float4*)linW)[i];
        if (tid < 40) slinb[tid] = linB[tid];
    }

    int tn = tid & 15;
    int tm = tid >> 4;
    int nbase = blockIdx.x * 64;

    u64 accZ2[4][2], accZ4[4][2], accM[4][2];
#pragma unroll
    for (int i = 0; i < 4; i++)
#pragma unroll
        for (int j = 0; j < 2; j++) { accZ2[i][j] = 0ull; accZ4[i][j] = 0ull; accM[i][j] = 0ull; }

    for (int c = 0; c < 4; c++) {
        __syncthreads();
        {
            int it = tid;
            int nl = it >> 2, f4 = it & 3;
            int node = nbase + nl;
            int kg = c * 16 + f4 * 4;
            float4 xlv = make_float4(0.f, 0.f, 0.f, 0.f), xhv = xlv, y2v = xlv, y4v = xlv;
            float dll2 = 0.f, dhh2 = 0.f;
            if (node < n) {
                xlv = *((const float4*)(g_xl + node * 64 + kg));
                xhv = *((const float4*)(g_xh + node * 64 + kg));
                y2v = *((const float4*)(g_y2 + node * 64 + kg));
                y4v = *((const float4*)(g_y4 + node * 64 + kg));
                float2 d = g_D2[node];
                dll2 = d.x * d.x; dhh2 = d.y * d.y;
            }
            int sb = nl * 17 + f4 * 4;
            bufA[sb + 0] = y2v.x + dll2 * xlv.x;
            bufA[sb + 1] = y2v.y + dll2 * xlv.y;
            bufA[sb + 2] = y2v.z + dll2 * xlv.z;
            bufA[sb + 3] = y2v.w + dll2 * xlv.w;
            bufB[sb + 0] = y4v.x + dhh2 * xhv.x;
            bufB[sb + 1] = y4v.y + dhh2 * xhv.y;
            bufB[sb + 2] = y4v.z + dhh2 * xhv.z;
            bufB[sb + 3] = y4v.w + dhh2 * xhv.w;
            bufC[sb + 0] = xlv.x; bufC[sb + 1] = xlv.y;
            bufC[sb + 2] = xlv.z; bufC[sb + 3] = xlv.w;
            bufD[sb + 0] = xhv.x; bufD[sb + 1] = xhv.y;
            bufD[sb + 2] = xhv.z; bufD[sb + 3] = xhv.w;
        }
        __syncthreads();
        const float* w2l = sw2l + c * 16 * 64;
        const float* w2r = sw2r + c * 16 * 64;
        const float* w4l = sw4l + c * 16 * 64;
        const float* w4r = sw4r + c * 16 * 64;
#pragma unroll 8
        for (int k = 0; k < 16; k++) {
            u64 a2p[4], a4p[4], xlp[4], xhp[4];
#pragma unroll
            for (int i = 0; i < 4; i++) {
                a2p[i] = bcast2(bufA[(tm * 4 + i) * 17 + k]);
                a4p[i] = bcast2(bufB[(tm * 4 + i) * 17 + k]);
                xlp[i] = bcast2(bufC[(tm * 4 + i) * 17 + k]);
                xhp[i] = bcast2(bufD[(tm * 4 + i) * 17 + k]);
            }
            ulonglong2 wz2l = *(const ulonglong2*)(w2l + k * 64 + tn * 4);
            ulonglong2 wz2r = *(const ulonglong2*)(w2r + k * 64 + tn * 4);
            ulonglong2 wz4l = *(const ulonglong2*)(w4l + k * 64 + tn * 4);
            ulonglong2 wz4r = *(const ulonglong2*)(w4r + k * 64 + tn * 4);
#pragma unroll
            for (int i = 0; i < 4; i++) {
                accZ2[i][0] = ffma2(a2p[i], wz2l.x, accZ2[i][0]);
                accZ2[i][1] = ffma2(a2p[i], wz2l.y, accZ2[i][1]);
                accZ2[i][0] = ffma2(xlp[i], wz2r.x, accZ2[i][0]);
                accZ2[i][1] = ffma2(xlp[i], wz2r.y, accZ2[i][1]);
                accZ4[i][0] = ffma2(a4p[i], wz4l.x, accZ4[i][0]);
                accZ4[i][1] = ffma2(a4p[i], wz4l.y, accZ4[i][1]);
                accZ4[i][0] = ffma2(xhp[i], wz4r.x, accZ4[i][0]);
                accZ4[i][1] = ffma2(xhp[i], wz4r.y, accZ4[i][1]);
            }
        }
    }

    for (int c = 0; c < 4; c++) {
        __syncthreads();
        {
            int it = tid;
            int nl = it >> 2, f4 = it & 3;
            int node = nbase + nl;
            int kg = c * 16 + f4 * 4;
            float4 xv = make_float4(0.f, 0.f, 0.f, 0.f);
            if (node < n) xv = __ldg((const float4*)(x + node * 64 + kg));
            int sb = nl * 17 + f4 * 4;
            bufA[sb + 0] = xv.x; bufA[sb + 1] = xv.y;
            bufA[sb + 2] = xv.z; bufA[sb + 3] = xv.w;
        }
        __syncthreads();
        const float* wm = swx + c * 16 * 64;
#pragma unroll 8
        for (int k = 0; k < 16; k++) {
            u64 ap[4];
#pragma unroll
            for (int i = 0; i < 4; i++) ap[i] = bcast2(bufA[(tm * 4 + i) * 17 + k]);
            ulonglong2 wv = *(const ulonglong2*)(wm + k * 64 + tn * 4);
#pragma unroll
            for (int i = 0; i < 4; i++) {
                accM[i][0] = ffma2(ap[i], wv.x, accM[i][0]);
                accM[i][1] = ffma2(ap[i], wv.y, accM[i][1]);
            }
        }
    }

    float e0 = __expf(__ldg(lam1)), e1 = __expf(__ldg(lam1 + 1));
    float lamxl = e0 / (e0 + e1), laml = e1 / (e0 + e1);
    float f0 = __expf(__ldg(lam2)), f1 = __expf(__ldg(lam2 + 1));
    float lamxh = f0 / (f0 + f1), lamh = f1 / (f0 + f1);

    __syncthreads();
#pragma unroll
    for (int i = 0; i < 4; i++) {
        int node = nbase + tm * 4 + i;
        float lamx = (node < n && __ldg(cc + node)) ? lamxl : lamxh;
        float* st = sxf + (tm * 4 + i) * 65 + tn * 4;
#pragma unroll
        for (int j = 0; j < 2; j++) {
            float2 m = unpack2(accM[i][j]);
            float2 z2 = unpack2(accZ2[i][j]);
            float2 z4 = unpack2(accZ4[i][j]);
            st[2 * j + 0] = fmaxf(lamx * m.x + laml * z2.x + lamh * z4.x, 0.f);
            st[2 * j + 1] = fmaxf(lamx * m.y + laml * z2.y + lamh * z4.y, 0.f);
        }
    }
    __syncthreads();

    int nl2 = tid >> 2;
    int og  = (tid & 3) * 10;
    int node = nbase + nl2;
    if (node < n) {
        u64 accv[5];
#pragma unroll
        for (int j = 0; j < 5; j++) accv[j] = pack2f(slinb[og + 2 * j], slinb[og + 2 * j + 1]);
        const float* xr = sxf + nl2 * 65;
#pragma unroll 8
        for (int k = 0; k < 64; k++) {
            u64 bp = bcast2(xr[k]);
            const u64* wr = (const u64*)(slin + k * 40 + og);
#pragma unroll
            for (int j = 0; j < 5; j++) accv[j] = ffma2(bp, wr[j], accv[j]);
        }
#pragma unroll
        for (int j = 0; j < 5; j++) {
            float2 p = unpack2(accv[j]);
            out[node * 40 + og + 2 * j]     = p.x;
            out[node * 40 + og + 2 * j + 1] = p.y;
        }
    }
}

// ---------------- host launcher --------------------------------------------
extern "C" void kernel_launch(void* const* d_in, const int* in_sizes, int n_in,
                              void* d_out, int out_size) {
    const float* x    = (const float*)d_in[0];
    const int*   ei   = (const int*)d_in[1];
    const int*   cc   = (const int*)d_in[2];
    const float* W1l  = (const float*)d_in[3];
    const float* W1r  = (const float*)d_in[4];
    const float* W2l  = (const float*)d_in[5];
    const float* W2r  = (const float*)d_in[6];
    const float* W3l  = (const float*)d_in[7];
    const float* W3r  = (const float*)d_in[8];
    const float* W4l  = (const float*)d_in[9];
    const float* W4r  = (const float*)d_in[10];
    const float* WX   = (const float*)d_in[11];
    const float* lam1 = (const float*)d_in[12];
    const float* lam2 = (const float*)d_in[13];
    const float* linW = (const float*)d_in[14];
    const float* linB = (const float*)d_in[15];
    float* out = (float*)d_out;

    int n = in_sizes[0] / 64;
    int E = in_sizes[1] / 2;
    const int* col = ei;
    const int* row = ei + E;
    int nblk = (n + 1023) / 1024;

    cudaFuncSetAttribute(k_dense1, cudaFuncAttributeMaxDynamicSharedMemorySize,
                         D1_SMEM_FLOATS * 4);
    cudaFuncSetAttribute(k_dense2, cudaFuncAttributeMaxDynamicSharedMemorySize,
                         D2_SMEM_FLOATS * 4);

    k_deg<<<(E + 255) / 256, 256>>>(col, row, cc, E);
    k_scanA<<<nblk, 1024>>>(n);
    k_scanC<<<nblk, 1024>>>(cc, n);
    k_scatter<<<(E + 255) / 256, 256>>>(row, E);
    k_gather0<<<(n + 7) / 8, 256>>>(cc, x, n);
    k_dense1<<<(n + 127) / 128, 256, D1_SMEM_FLOATS * 4>>>(x, cc, W1l, W1r, W3l, W3r, n);
    k_gather1<<<(n + 7) / 8, 256>>>(n);
    k_dense2<<<(n + 63) / 64, 256, D2_SMEM_FLOATS * 4>>>(x, cc, W2l, W2r, W4l, W4r,
                                                         WX, lam1, lam2, linW, linB,
                                                         out, n);
}